// round 16
// baseline (speedup 1.0000x reference)
#include <cuda_runtime.h>
#include <cuda_fp16.h>
#include <cstdint>

#define NN 16384
#define CC 64
#define JJ 16
#define OO 128
#define RSP 144                 // proj row stride bytes (128 data + 16 pad; 9 quads)
#define PBUF (64 * RSP)         // 9216

// smem layout (bytes)
#define SM_ADJ 0                // 1024 ints = 4096
#define SM_P   4096             // 2 x PBUF = 18432
#define SM_CE  22528            // fp16 centers: 64 pts x 128 B = 8192
#define SMEMTOT 30720

// fp16 copy of x: [b][n][c]
__device__ __half g_xh[2 * NN * CC];            // 4 MB
// A fragments pre-baked (fp16 pairs), m16n8k16 layout:
// word i = ((((j*4+c)*4+mi)*2+mh)*32 + lane)*4 + aidx
__device__ unsigned char g_Wf[JJ * 4 * 4 * 2 * 32 * 16];   // 256 KB

// fused prep: blocks [0,256) convert x (16 words out/thread); blocks [256,512) bake W
__global__ void prep(const float* __restrict__ x, const float* __restrict__ w) {
    int bx = blockIdx.x, tid = threadIdx.x;
    if (bx < 256) {
        int i = bx * 256 + tid;                  // 65536 threads, 4 uint4 out each
        const float4* src = (const float4*)x + i * 8;
        uint4* dst = (uint4*)g_xh + i * 4;
        #pragma unroll
        for (int q = 0; q < 4; q++) {
            float4 v0 = src[2*q], v1 = src[2*q+1];
            uint4 o;
            asm("cvt.rn.f16x2.f32 %0, %1, %2;" : "=r"(o.x) : "f"(v0.y), "f"(v0.x));
            asm("cvt.rn.f16x2.f32 %0, %1, %2;" : "=r"(o.y) : "f"(v0.w), "f"(v0.z));
            asm("cvt.rn.f16x2.f32 %0, %1, %2;" : "=r"(o.z) : "f"(v1.y), "f"(v1.x));
            asm("cvt.rn.f16x2.f32 %0, %1, %2;" : "=r"(o.w) : "f"(v1.w), "f"(v1.z));
            dst[q] = o;
        }
    } else {
        int i = (bx - 256) * 256 + tid;          // 65536 words
        int aidx = i & 3;
        int lane = (i >> 2) & 31;
        int mh   = (i >> 7) & 1;
        int mi   = (i >> 8) & 3;
        int c    = (i >> 10) & 3;
        int j    = i >> 12;
        int g = lane >> 2, tg = lane & 3;
        int o  = mi * 32 + mh * 16 + (aidx & 1) * 8 + g;
        int k0 = c * 16 + (aidx >> 1) * 8 + 2 * tg;
        float v0 = w[(o * CC + k0) * JJ + j];
        float v1 = w[(o * CC + k0 + 1) * JJ + j];
        uint32_t r; asm("cvt.rn.f16x2.f32 %0, %1, %2;" : "=r"(r) : "f"(v1), "f"(v0));
        ((uint32_t*)g_Wf)[i] = r;
    }
}

__device__ __forceinline__ uint32_t smem_u32(const void* p) {
    uint32_t a; asm("{ .reg .u64 t; cvta.to.shared.u64 t, %1; cvt.u32.u64 %0, t; }" : "=r"(a) : "l"(p));
    return a;
}
__device__ __forceinline__ uint32_t pkh(float flo, float fhi) {   // low half <- flo
    uint32_t r; asm("cvt.rn.f16x2.f32 %0, %1, %2;" : "=r"(r) : "f"(fhi), "f"(flo));
    return r;
}
__device__ __forceinline__ void ldm4(uint32_t* r, uint32_t addr) {
    asm volatile("ldmatrix.sync.aligned.m8n8.x4.shared.b16 {%0,%1,%2,%3}, [%4];"
        : "=r"(r[0]), "=r"(r[1]), "=r"(r[2]), "=r"(r[3]) : "r"(addr));
}
// accumulate in place: D == C
__device__ __forceinline__ void mma16816(float* c, const uint32_t* a, uint32_t b0, uint32_t b1) {
    asm volatile("mma.sync.aligned.m16n8k16.row.col.f32.f16.f16.f32 "
        "{%0,%1,%2,%3},{%4,%5,%6,%7},{%8,%9},{%0,%1,%2,%3};"
        : "+f"(c[0]), "+f"(c[1]), "+f"(c[2]), "+f"(c[3])
        : "r"(a[0]), "r"(a[1]), "r"(a[2]), "r"(a[3]), "r"(b0), "r"(b1));
}
// first chunk: D <- A*B + 0 (separate zero C regs; no acc pre-zeroing)
__device__ __forceinline__ void mma16816_z(float* d, const uint32_t* a, uint32_t b0, uint32_t b1,
                                           const float* z) {
    asm volatile("mma.sync.aligned.m16n8k16.row.col.f32.f16.f16.f32 "
        "{%0,%1,%2,%3},{%4,%5,%6,%7},{%8,%9},{%10,%11,%12,%13};"
        : "=f"(d[0]), "=f"(d[1]), "=f"(d[2]), "=f"(d[3])
        : "r"(a[0]), "r"(a[1]), "r"(a[2]), "r"(a[3]), "r"(b0), "r"(b1),
          "f"(z[0]), "f"(z[1]), "f"(z[2]), "f"(z[3]));
}

__global__ __launch_bounds__(256, 2) void sconv_kernel(
    const float* __restrict__ x, const int* __restrict__ adj, float* __restrict__ out)
{
    extern __shared__ unsigned char S[];
    const uint32_t sb = smem_u32(S);
    const int tid = threadIdx.x, lid = tid & 31, wid = tid >> 5;
    const int b  = blockIdx.x >> 8;               // 512 blocks: 256 per batch
    const int n0 = (blockIdx.x & 255) << 6;       // 64 points per block
    const float* xb = x + (size_t)b * NN * CC;
    const __half* xhb = g_xh + (size_t)b * NN * CC;

    const int p_ = tid >> 2, l = tid & 3;         // builder: 4 lanes/point, 16 ch each

    // consumer mapping: 4 m-warps x 2 n-warps; warp tile m32 x n32
    const int mi = wid & 3;
    const int nw = (wid >> 2) * 32;
    const int g8 = lid >> 3, r8 = lid & 7;
    const uint32_t boff = (uint32_t)((nw + r8 + 8 * (g8 >> 1)) * RSP + (g8 & 1) * 16);
    const int r4 = lid >> 2, c4 = lid & 3;

    int* adjS = (int*)S;
    {
        int base = (b * NN + n0) * 17;
        #pragma unroll
        for (int i = 0; i < 4; i++) {
            int idx = tid + 256 * i;              // 1024 ints (skip self col 0)
            adjS[idx] = adj[base + (idx >> 4) * 17 + 1 + (idx & 15)];
        }
    }

    // center values -> fp16 smem (32 B per builder lane), frees 16 registers
    const uint32_t ceaddr = sb + SM_CE + (uint32_t)(p_ * 128 + l * 32);
    {
        const float4* cp_ = (const float4*)(xb + (size_t)(n0 + p_) * CC + l * 16);
        float4 v0 = cp_[0], v1 = cp_[1], v2 = cp_[2], v3 = cp_[3];
        uint4 h0, h1;
        h0.x = pkh(v0.x, v0.y); h0.y = pkh(v0.z, v0.w);
        h0.z = pkh(v1.x, v1.y); h0.w = pkh(v1.z, v1.w);
        h1.x = pkh(v2.x, v2.y); h1.y = pkh(v2.z, v2.w);
        h1.z = pkh(v3.x, v3.y); h1.w = pkh(v3.z, v3.w);
        asm volatile("st.shared.v4.b32 [%0], {%1,%2,%3,%4};" :: "r"(ceaddr),
            "r"(h0.x), "r"(h0.y), "r"(h0.z), "r"(h0.w) : "memory");
        asm volatile("st.shared.v4.b32 [%0], {%1,%2,%3,%4};" :: "r"(ceaddr + 16),
            "r"(h1.x), "r"(h1.y), "r"(h1.z), "r"(h1.w) : "memory");
    }
    __syncthreads();   // adjS + ce ready

    // direct fp16 gather into registers (2 x LDG.128 per thread)
    uint4 pf0, pf1;
    auto prefetch = [&](int j) {
        int gi = adjS[p_ * 16 + j];
        const uint4* src = (const uint4*)(xhb + (size_t)gi * CC + l * 16);
        pf0 = src[0];
        pf1 = src[1];
    };
    auto buildP = [&](int j) {
        uint32_t ch[8];
        asm volatile("ld.shared.v4.b32 {%0,%1,%2,%3}, [%4];"
            : "=r"(ch[0]), "=r"(ch[1]), "=r"(ch[2]), "=r"(ch[3]) : "r"(ceaddr));
        asm volatile("ld.shared.v4.b32 {%0,%1,%2,%3}, [%4];"
            : "=r"(ch[4]), "=r"(ch[5]), "=r"(ch[6]), "=r"(ch[7]) : "r"(ceaddr + 16));
        const uint32_t* hs0 = (const uint32_t*)&pf0;
        const uint32_t* hs1 = (const uint32_t*)&pf1;
        float d[16]; float ssq = 0.f;
        #pragma unroll
        for (int q = 0; q < 4; q++) {
            float2 f = __half22float2(*(const __half2*)&hs0[q]);
            float2 c = __half22float2(*(const __half2*)&ch[q]);
            d[2*q]   = f.x - c.x;
            d[2*q+1] = f.y - c.y;
        }
        #pragma unroll
        for (int q = 0; q < 4; q++) {
            float2 f = __half22float2(*(const __half2*)&hs1[q]);
            float2 c = __half22float2(*(const __half2*)&ch[4+q]);
            d[8+2*q]   = f.x - c.x;
            d[8+2*q+1] = f.y - c.y;
        }
        #pragma unroll
        for (int q = 0; q < 16; q++) ssq = fmaf(d[q], d[q], ssq);
        ssq += __shfl_xor_sync(0xffffffffu, ssq, 1);
        ssq += __shfl_xor_sync(0xffffffffu, ssq, 2);
        float s = rsqrtf(2.0f * ssq);             // 1/(sqrt2*||diff||)
        uint32_t h[8];
        #pragma unroll
        for (int q = 0; q < 8; q++) h[q] = pkh(d[2*q] * s, d[2*q+1] * s);
        unsigned char* P = S + SM_P + (j & 1) * PBUF + p_ * RSP + l * 32;
        ((uint4*)P)[0] = ((uint4*)h)[0];
        ((uint4*)P)[1] = ((uint4*)h)[1];
    };

    float acc[32], mx[32];
    #pragma unroll
    for (int i = 0; i < 32; i++) mx[i] = 0.f;     // relu+max -> init 0
    const float z4[4] = {0.f, 0.f, 0.f, 0.f};

    prefetch(0);
    buildP(0);
    __syncthreads();

    for (int j = 0; j < JJ; j++) {
        if (j + 1 < JJ) prefetch(j + 1);          // LDG issues here; consumed after mma
        const uint32_t Pb = sb + SM_P + (j & 1) * PBUF;
        #pragma unroll
        for (int c = 0; c < 4; c++) {
            // A: 2 LDG.128 from fragment-layout gmem (L1-hot)
            const unsigned char* ab = g_Wf + ((size_t)(((j * 4 + c) * 4 + mi) * 2) << 9) + (lid << 4);
            uint32_t a0[4], a1[4];
            *(uint4*)a0 = *(const uint4*)(ab);
            *(uint4*)a1 = *(const uint4*)(ab + 512);
            // B: 2 ldmatrix.x4 -> n32 x k16
            uint32_t bh[8];
            ldm4(bh,     Pb + boff + 32 * c);
            ldm4(bh + 4, Pb + boff + 16 * RSP + 32 * c);
            #pragma unroll
            for (int q = 0; q < 2; q++) {
                #pragma unroll
                for (int h2 = 0; h2 < 2; h2++) {
                    int nt = 2 * q + h2;
                    uint32_t b0 = bh[4*q + 2*h2], b1 = bh[4*q + 2*h2 + 1];
                    if (c == 0) {
                        mma16816_z(&acc[nt * 4],      a0, b0, b1, z4);
                        mma16816_z(&acc[16 + nt * 4], a1, b0, b1, z4);
                    } else {
                        mma16816(&acc[nt * 4],      a0, b0, b1);
                        mma16816(&acc[16 + nt * 4], a1, b0, b1);
                    }
                }
            }
        }
        #pragma unroll
        for (int i = 0; i < 32; i++) mx[i] = fmaxf(mx[i], acc[i]);

        if (j + 1 < JJ) buildP(j + 1);
        __syncthreads();
    }

    // write out[b][o][n]
    {
        const int m0 = mi * 32;
        #pragma unroll
        for (int mh = 0; mh < 2; mh++) {
            #pragma unroll
            for (int nt = 0; nt < 4; nt++) {
                float* a = &mx[mh * 16 + nt * 4];
                int ncol = n0 + nw + nt * 8 + 2 * c4;
                int o1 = m0 + 16 * mh + r4;
                *(float2*)(out + (size_t)(b * OO + o1) * NN + ncol)     = make_float2(a[0], a[1]);
                *(float2*)(out + (size_t)(b * OO + o1 + 8) * NN + ncol) = make_float2(a[2], a[3]);
            }
        }
    }
}

extern "C" void kernel_launch(void* const* d_in, const int* in_sizes, int n_in,
                              void* d_out, int out_size) {
    const float* x   = (const float*)d_in[0];
    const int*   adj = (const int*)d_in[1];
    const float* w   = (const float*)d_in[2];
    float* out = (float*)d_out;

    cudaFuncSetAttribute(sconv_kernel, cudaFuncAttributeMaxDynamicSharedMemorySize, SMEMTOT);
    prep<<<512, 256>>>(x, w);
    sconv_kernel<<<512, 256, SMEMTOT>>>(x, adj, out);
}

// round 17
// speedup vs baseline: 1.0416x; 1.0416x over previous
#include <cuda_runtime.h>
#include <cuda_fp16.h>
#include <cstdint>

#define NN 16384
#define CC 64
#define JJ 16
#define OO 128
#define RSP 144                 // proj row stride bytes (128 data + 16 pad; 9 quads)
#define PBUF (64 * RSP)         // 9216

// smem layout (bytes)
#define SM_ADJ 0                // 1024 ints = 4096
#define SM_P   4096             // 2 x PBUF = 18432
#define SM_CE  22528            // fp16 centers: 64 pts x 128 B = 8192
#define SMEMTOT 30720

// fp16 copy of x: [b][n][c]
__device__ __half g_xh[2 * NN * CC];            // 4 MB
// A fragments pre-baked (fp16 pairs), m16n8k16 layout:
// word i = ((((j*4+c)*4+mi)*2+mh)*32 + lane)*4 + aidx
__device__ unsigned char g_Wf[JJ * 4 * 4 * 2 * 32 * 16];   // 256 KB

// fused prep: blocks [0,1024) convert x (4 words out/thread, 262K threads);
//             blocks [1024,1280) bake W fragments
__global__ void prep(const float* __restrict__ x, const float* __restrict__ w) {
    int bx = blockIdx.x, tid = threadIdx.x;
    if (bx < 1024) {
        int i = bx * 256 + tid;                  // 262144 threads, 1 uint4 out each
        const float4* src = (const float4*)x + i * 2;
        float4 v0 = src[0], v1 = src[1];
        uint4 o;
        asm("cvt.rn.f16x2.f32 %0, %1, %2;" : "=r"(o.x) : "f"(v0.y), "f"(v0.x));
        asm("cvt.rn.f16x2.f32 %0, %1, %2;" : "=r"(o.y) : "f"(v0.w), "f"(v0.z));
        asm("cvt.rn.f16x2.f32 %0, %1, %2;" : "=r"(o.z) : "f"(v1.y), "f"(v1.x));
        asm("cvt.rn.f16x2.f32 %0, %1, %2;" : "=r"(o.w) : "f"(v1.w), "f"(v1.z));
        ((uint4*)g_xh)[i] = o;
    } else {
        int i = (bx - 1024) * 256 + tid;         // 65536 words
        int aidx = i & 3;
        int lane = (i >> 2) & 31;
        int mh   = (i >> 7) & 1;
        int mi   = (i >> 8) & 3;
        int c    = (i >> 10) & 3;
        int j    = i >> 12;
        int g = lane >> 2, tg = lane & 3;
        int o  = mi * 32 + mh * 16 + (aidx & 1) * 8 + g;
        int k0 = c * 16 + (aidx >> 1) * 8 + 2 * tg;
        float v0 = w[(o * CC + k0) * JJ + j];
        float v1 = w[(o * CC + k0 + 1) * JJ + j];
        uint32_t r; asm("cvt.rn.f16x2.f32 %0, %1, %2;" : "=r"(r) : "f"(v1), "f"(v0));
        ((uint32_t*)g_Wf)[i] = r;
    }
}

__device__ __forceinline__ uint32_t smem_u32(const void* p) {
    uint32_t a; asm("{ .reg .u64 t; cvta.to.shared.u64 t, %1; cvt.u32.u64 %0, t; }" : "=r"(a) : "l"(p));
    return a;
}
__device__ __forceinline__ uint32_t pkh(float flo, float fhi) {   // low half <- flo
    uint32_t r; asm("cvt.rn.f16x2.f32 %0, %1, %2;" : "=r"(r) : "f"(fhi), "f"(flo));
    return r;
}
__device__ __forceinline__ void ldm4(uint32_t* r, uint32_t addr) {
    asm volatile("ldmatrix.sync.aligned.m8n8.x4.shared.b16 {%0,%1,%2,%3}, [%4];"
        : "=r"(r[0]), "=r"(r[1]), "=r"(r[2]), "=r"(r[3]) : "r"(addr));
}
// accumulate in place: D == C
__device__ __forceinline__ void mma16816(float* c, const uint32_t* a, uint32_t b0, uint32_t b1) {
    asm volatile("mma.sync.aligned.m16n8k16.row.col.f32.f16.f16.f32 "
        "{%0,%1,%2,%3},{%4,%5,%6,%7},{%8,%9},{%0,%1,%2,%3};"
        : "+f"(c[0]), "+f"(c[1]), "+f"(c[2]), "+f"(c[3])
        : "r"(a[0]), "r"(a[1]), "r"(a[2]), "r"(a[3]), "r"(b0), "r"(b1));
}
// first chunk: D <- A*B + 0 (separate zero C regs; no acc pre-zeroing)
__device__ __forceinline__ void mma16816_z(float* d, const uint32_t* a, uint32_t b0, uint32_t b1,
                                           const float* z) {
    asm volatile("mma.sync.aligned.m16n8k16.row.col.f32.f16.f16.f32 "
        "{%0,%1,%2,%3},{%4,%5,%6,%7},{%8,%9},{%10,%11,%12,%13};"
        : "=f"(d[0]), "=f"(d[1]), "=f"(d[2]), "=f"(d[3])
        : "r"(a[0]), "r"(a[1]), "r"(a[2]), "r"(a[3]), "r"(b0), "r"(b1),
          "f"(z[0]), "f"(z[1]), "f"(z[2]), "f"(z[3]));
}

__global__ __launch_bounds__(256, 2) void sconv_kernel(
    const float* __restrict__ x, const int* __restrict__ adj, float* __restrict__ out)
{
    extern __shared__ unsigned char S[];
    const uint32_t sb = smem_u32(S);
    const int tid = threadIdx.x, lid = tid & 31, wid = tid >> 5;
    const int b  = blockIdx.x >> 8;               // 512 blocks: 256 per batch
    const int n0 = (blockIdx.x & 255) << 6;       // 64 points per block
    const float* xb = x + (size_t)b * NN * CC;
    const __half* xhb = g_xh + (size_t)b * NN * CC;

    const int p_ = tid >> 2, l = tid & 3;         // builder: 4 lanes/point, 16 ch each

    // consumer mapping: 4 m-warps x 2 n-warps; warp tile m32 x n32
    const int mi = wid & 3;
    const int nw = (wid >> 2) * 32;
    const int g8 = lid >> 3, r8 = lid & 7;
    const uint32_t boff = (uint32_t)((nw + r8 + 8 * (g8 >> 1)) * RSP + (g8 & 1) * 16);
    const int r4 = lid >> 2, c4 = lid & 3;

    int* adjS = (int*)S;
    {
        int base = (b * NN + n0) * 17;
        #pragma unroll
        for (int i = 0; i < 4; i++) {
            int idx = tid + 256 * i;              // 1024 ints (skip self col 0)
            adjS[idx] = adj[base + (idx >> 4) * 17 + 1 + (idx & 15)];
        }
    }

    // center values -> fp16 smem (32 B per builder lane), frees 16 registers
    const uint32_t ceaddr = sb + SM_CE + (uint32_t)(p_ * 128 + l * 32);
    {
        const float4* cp_ = (const float4*)(xb + (size_t)(n0 + p_) * CC + l * 16);
        float4 v0 = cp_[0], v1 = cp_[1], v2 = cp_[2], v3 = cp_[3];
        uint4 h0, h1;
        h0.x = pkh(v0.x, v0.y); h0.y = pkh(v0.z, v0.w);
        h0.z = pkh(v1.x, v1.y); h0.w = pkh(v1.z, v1.w);
        h1.x = pkh(v2.x, v2.y); h1.y = pkh(v2.z, v2.w);
        h1.z = pkh(v3.x, v3.y); h1.w = pkh(v3.z, v3.w);
        asm volatile("st.shared.v4.b32 [%0], {%1,%2,%3,%4};" :: "r"(ceaddr),
            "r"(h0.x), "r"(h0.y), "r"(h0.z), "r"(h0.w) : "memory");
        asm volatile("st.shared.v4.b32 [%0], {%1,%2,%3,%4};" :: "r"(ceaddr + 16),
            "r"(h1.x), "r"(h1.y), "r"(h1.z), "r"(h1.w) : "memory");
    }
    __syncthreads();   // adjS + ce ready

    // direct fp16 gather into registers (2 x LDG.128 per thread)
    uint4 pf0, pf1;
    auto prefetch = [&](int j) {
        int gi = adjS[p_ * 16 + j];
        const uint4* src = (const uint4*)(xhb + (size_t)gi * CC + l * 16);
        pf0 = src[0];
        pf1 = src[1];
    };
    auto buildP = [&](int j) {
        uint32_t ch[8];
        asm volatile("ld.shared.v4.b32 {%0,%1,%2,%3}, [%4];"
            : "=r"(ch[0]), "=r"(ch[1]), "=r"(ch[2]), "=r"(ch[3]) : "r"(ceaddr));
        asm volatile("ld.shared.v4.b32 {%0,%1,%2,%3}, [%4];"
            : "=r"(ch[4]), "=r"(ch[5]), "=r"(ch[6]), "=r"(ch[7]) : "r"(ceaddr + 16));
        const uint32_t* hs0 = (const uint32_t*)&pf0;
        const uint32_t* hs1 = (const uint32_t*)&pf1;
        float d[16]; float ssq = 0.f;
        #pragma unroll
        for (int q = 0; q < 4; q++) {
            float2 f = __half22float2(*(const __half2*)&hs0[q]);
            float2 c = __half22float2(*(const __half2*)&ch[q]);
            d[2*q]   = f.x - c.x;
            d[2*q+1] = f.y - c.y;
        }
        #pragma unroll
        for (int q = 0; q < 4; q++) {
            float2 f = __half22float2(*(const __half2*)&hs1[q]);
            float2 c = __half22float2(*(const __half2*)&ch[4+q]);
            d[8+2*q]   = f.x - c.x;
            d[8+2*q+1] = f.y - c.y;
        }
        #pragma unroll
        for (int q = 0; q < 16; q++) ssq = fmaf(d[q], d[q], ssq);
        ssq += __shfl_xor_sync(0xffffffffu, ssq, 1);
        ssq += __shfl_xor_sync(0xffffffffu, ssq, 2);
        float s = rsqrtf(2.0f * ssq);             // 1/(sqrt2*||diff||)
        uint32_t h[8];
        #pragma unroll
        for (int q = 0; q < 8; q++) h[q] = pkh(d[2*q] * s, d[2*q+1] * s);
        unsigned char* P = S + SM_P + (j & 1) * PBUF + p_ * RSP + l * 32;
        ((uint4*)P)[0] = ((uint4*)h)[0];
        ((uint4*)P)[1] = ((uint4*)h)[1];
    };

    float acc[32], mx[32];
    #pragma unroll
    for (int i = 0; i < 32; i++) mx[i] = 0.f;     // relu+max -> init 0
    const float z4[4] = {0.f, 0.f, 0.f, 0.f};

    prefetch(0);
    buildP(0);
    __syncthreads();

    for (int j = 0; j < JJ; j++) {
        if (j + 1 < JJ) prefetch(j + 1);          // LDG issues here; consumed after mma
        const uint32_t Pb = sb + SM_P + (j & 1) * PBUF;
        #pragma unroll
        for (int c = 0; c < 4; c++) {
            // A: 2 LDG.128 from fragment-layout gmem (L1-hot)
            const unsigned char* ab = g_Wf + ((size_t)(((j * 4 + c) * 4 + mi) * 2) << 9) + (lid << 4);
            uint32_t a0[4], a1[4];
            *(uint4*)a0 = *(const uint4*)(ab);
            *(uint4*)a1 = *(const uint4*)(ab + 512);
            // B: 2 ldmatrix.x4 -> n32 x k16
            uint32_t bh[8];
            ldm4(bh,     Pb + boff + 32 * c);
            ldm4(bh + 4, Pb + boff + 16 * RSP + 32 * c);
            #pragma unroll
            for (int q = 0; q < 2; q++) {
                #pragma unroll
                for (int h2 = 0; h2 < 2; h2++) {
                    int nt = 2 * q + h2;
                    uint32_t b0 = bh[4*q + 2*h2], b1 = bh[4*q + 2*h2 + 1];
                    if (c == 0) {
                        mma16816_z(&acc[nt * 4],      a0, b0, b1, z4);
                        mma16816_z(&acc[16 + nt * 4], a1, b0, b1, z4);
                    } else {
                        mma16816(&acc[nt * 4],      a0, b0, b1);
                        mma16816(&acc[16 + nt * 4], a1, b0, b1);
                    }
                }
            }
        }
        #pragma unroll
        for (int i = 0; i < 32; i++) mx[i] = fmaxf(mx[i], acc[i]);

        if (j + 1 < JJ) buildP(j + 1);
        __syncthreads();
    }

    // write out[b][o][n]
    {
        const int m0 = mi * 32;
        #pragma unroll
        for (int mh = 0; mh < 2; mh++) {
            #pragma unroll
            for (int nt = 0; nt < 4; nt++) {
                float* a = &mx[mh * 16 + nt * 4];
                int ncol = n0 + nw + nt * 8 + 2 * c4;
                int o1 = m0 + 16 * mh + r4;
                *(float2*)(out + (size_t)(b * OO + o1) * NN + ncol)     = make_float2(a[0], a[1]);
                *(float2*)(out + (size_t)(b * OO + o1 + 8) * NN + ncol) = make_float2(a[2], a[3]);
            }
        }
    }
}

extern "C" void kernel_launch(void* const* d_in, const int* in_sizes, int n_in,
                              void* d_out, int out_size) {
    const float* x   = (const float*)d_in[0];
    const int*   adj = (const int*)d_in[1];
    const float* w   = (const float*)d_in[2];
    float* out = (float*)d_out;

    cudaFuncSetAttribute(sconv_kernel, cudaFuncAttributeMaxDynamicSharedMemorySize, SMEMTOT);
    prep<<<1280, 256>>>(x, w);
    sconv_kernel<<<512, 256, SMEMTOT>>>(x, adj, out);
}